// round 5
// baseline (speedup 1.0000x reference)
#include <cuda_runtime.h>
#include <cstdint>

#define Bn 32
#define Fn 64
#define Ln 8192
#define Pn 96
#define SR 132    // xn/q/v tile row stride (floats)
#define SRY 130   // y tile row stride (floats)
#define SRW 132   // Wlin tile row stride

typedef unsigned long long ull;

// ---------------- scratch (device globals) ----------------
__device__ float g_mean[Bn * Fn];
__device__ float g_istd[Bn * Fn];
__device__ float g_stdp[Bn * Fn];
__device__ float g_KV[Bn * 512];
__device__ float g_Z[Bn * 64];
__device__ float g_M[Bn * Pn * Fn];
// pre-folded, duplicated (f32x2) weights: layout [k(=input dim)][e(=output dim)]
__device__ float2 g_Wqp[4096], g_Wkp[4096], g_Wvp[4096], g_Wop[4096];
__device__ float g_dq[64], g_cq[64], g_dk[64], g_ck[64], g_dv[64], g_cv[64];

// ---------------- helpers ----------------
__device__ __forceinline__ void fma2(ull& d, ull a, ull b) {
    asm("fma.rn.f32x2 %0, %1, %2, %0;" : "+l"(d) : "l"(a), "l"(b));
}
__device__ __forceinline__ float2 upk(ull v) {
    float2 r;
    asm("mov.b64 {%0, %1}, %2;" : "=f"(r.x), "=f"(r.y) : "l"(v));
    return r;
}
__device__ __forceinline__ ull pk2(float a, float b) {
    ull r;
    asm("mov.b64 %0, {%1, %2};" : "=l"(r) : "f"(a), "f"(b));
    return r;
}
__device__ __forceinline__ float phi_fn(float v) {
    return v > 0.f ? v + 1.f : __expf(v);   // elu(x)+1
}

// 64-deep GEMM micro-tile: 4 consecutive outputs (e0..e0+3) x 8 consecutive l
// (4 f32x2 pairs at l0..l0+7). hb = tile + l0, wbase = w_ull + e0.
// All 4 loads per k are dense LDS.128: h = 4x16B lines 8-way bcast (1 wf),
// w = 8x16B lines = 128 contiguous bytes (1 wf).
__device__ __forceinline__ void gemm_tile(const float* __restrict__ hb,
                                          const ull* __restrict__ wbase,
                                          ull acc[4][4]) {
#pragma unroll
    for (int i = 0; i < 4; i++) { acc[i][0] = acc[i][1] = acc[i][2] = acc[i][3] = 0ULL; }
#pragma unroll 8
    for (int k = 0; k < 64; k++) {
        ulonglong2 h01 = *(const ulonglong2*)(hb + k * SR);
        ulonglong2 h23 = *(const ulonglong2*)(hb + k * SR + 4);
        ulonglong2 w01 = *(const ulonglong2*)(wbase + k * 64);
        ulonglong2 w23 = *(const ulonglong2*)(wbase + k * 64 + 2);
        fma2(acc[0][0], w01.x, h01.x); fma2(acc[0][1], w01.x, h01.y);
        fma2(acc[0][2], w01.x, h23.x); fma2(acc[0][3], w01.x, h23.y);
        fma2(acc[1][0], w01.y, h01.x); fma2(acc[1][1], w01.y, h01.y);
        fma2(acc[1][2], w01.y, h23.x); fma2(acc[1][3], w01.y, h23.y);
        fma2(acc[2][0], w23.x, h01.x); fma2(acc[2][1], w23.x, h01.y);
        fma2(acc[2][2], w23.x, h23.x); fma2(acc[2][3], w23.x, h23.y);
        fma2(acc[3][0], w23.y, h01.x); fma2(acc[3][1], w23.y, h01.y);
        fma2(acc[3][2], w23.y, h23.x); fma2(acc[3][3], w23.y, h23.y);
    }
}

// ---------------- kernel 0: zero accumulators ----------------
__global__ void k_zero() {
    int i = blockIdx.x * blockDim.x + threadIdx.x;
    if (i < Bn * 512)      g_KV[i] = 0.f;
    if (i < Bn * 64)       g_Z[i]  = 0.f;
    if (i < Bn * Pn * Fn)  g_M[i]  = 0.f;
}

// ---------------- prep: fold LN into weights, duplicate pairs ----------------
__global__ void __launch_bounds__(256) k_prep(
    const float* __restrict__ lnw, const float* __restrict__ lnb,
    const float* __restrict__ Wq, const float* __restrict__ bq,
    const float* __restrict__ Wk, const float* __restrict__ bk,
    const float* __restrict__ Wv, const float* __restrict__ bv,
    const float* __restrict__ Wo)
{
    int tid = threadIdx.x;
#pragma unroll
    for (int i = 0; i < 16; i++) {
        int idx = tid + i * 256;          // idx = f*64 + e
        int f = idx >> 6, e = idx & 63;
        float lw = lnw[f];
        float wq = Wq[e * 64 + f] * lw;  g_Wqp[idx] = make_float2(wq, wq);
        float wk = Wk[e * 64 + f] * lw;  g_Wkp[idx] = make_float2(wk, wk);
        float wv = Wv[e * 64 + f] * lw;  g_Wvp[idx] = make_float2(wv, wv);
        float wo = Wo[e * 64 + f];       g_Wop[idx] = make_float2(wo, wo);  // [k=e_att][fo]
    }
    if (tid < 64) {
        int e = tid;
        float dq = 0.f, cq = 0.f, dk = 0.f, ck = 0.f, dv = 0.f, cv = 0.f;
        for (int f = 0; f < 64; f++) {
            float lw = lnw[f], lb2 = lnb[f];
            float wq = Wq[e * 64 + f], wk = Wk[e * 64 + f], wv = Wv[e * 64 + f];
            dq += wq * lw;  cq = fmaf(lb2, wq, cq);
            dk += wk * lw;  ck = fmaf(lb2, wk, ck);
            dv += wv * lw;  cv = fmaf(lb2, wv, cv);
        }
        g_dq[e] = dq; g_cq[e] = cq + bq[e];
        g_dk[e] = dk; g_ck[e] = ck + bk[e];
        g_dv[e] = dv; g_cv[e] = cv + bv[e];
    }
}

// ---------------- kernel 1: RevIN stats per (b,f) ----------------
__global__ void __launch_bounds__(256) k_stats(const float* __restrict__ x) {
    int bf = blockIdx.x;
    const float4* p = (const float4*)(x + (size_t)bf * Ln);
    float s1 = 0.f, s2 = 0.f;
    for (int i = threadIdx.x; i < Ln / 4; i += 256) {
        float4 v = p[i];
        s1 += (v.x + v.y) + (v.z + v.w);
        s2 = fmaf(v.x, v.x, s2); s2 = fmaf(v.y, v.y, s2);
        s2 = fmaf(v.z, v.z, s2); s2 = fmaf(v.w, v.w, s2);
    }
    __shared__ float r1[256], r2[256];
    r1[threadIdx.x] = s1; r2[threadIdx.x] = s2;
    __syncthreads();
    for (int s = 128; s > 0; s >>= 1) {
        if (threadIdx.x < s) {
            r1[threadIdx.x] += r1[threadIdx.x + s];
            r2[threadIdx.x] += r2[threadIdx.x + s];
        }
        __syncthreads();
    }
    if (threadIdx.x == 0) {
        float S1 = r1[0], S2 = r2[0];
        float mean = S1 / (float)Ln;
        float var = (S2 - S1 * mean) / (float)(Ln - 1);
        var = fmaxf(var, 0.f);
        float stdp = sqrtf(var) + 1e-5f;
        g_mean[bf] = mean; g_stdp[bf] = stdp; g_istd[bf] = 1.f / stdp;
    }
}

// ---------------- kernel 2: K/V projections + KV,Z ----------------
__global__ void __launch_bounds__(256, 2) k_kv(
    const float* __restrict__ x, const float* __restrict__ gamma, const float* __restrict__ beta)
{
    extern __shared__ float sm[];
    float*  xns = sm;                          // 64*SR; later holds phi(K)
    float*  vb  = sm + 64 * SR;                // 64*SR
    float2* wb  = (float2*)(sm + 2 * 64 * SR); // 4096 float2
    __shared__ float mus[128], rss[128], As[64], Cs[64];
    __shared__ float dks[64], cks[64], dvs[64], cvs[64];

    int b = blockIdx.y, tid = threadIdx.x;
    int l0b = blockIdx.x * 128;

    if (tid < 64) {
        float a = gamma[tid] * g_istd[b * 64 + tid];
        As[tid] = a;
        Cs[tid] = beta[tid] - g_mean[b * 64 + tid] * a;
        dks[tid] = g_dk[tid]; cks[tid] = g_ck[tid];
        dvs[tid] = g_dv[tid]; cvs[tid] = g_cv[tid];
    }
    {   // wb <- Wv packed
        const float4* src = (const float4*)g_Wvp;
        float4* dst = (float4*)wb;
#pragma unroll
        for (int i = 0; i < 8; i++) dst[tid + i * 256] = src[tid + i * 256];
    }
    __syncthreads();
#pragma unroll
    for (int i = 0; i < 8; i++) {
        int idx = tid + i * 256;
        int f = idx >> 5, c = idx & 31;
        float4 v = *(const float4*)(x + ((size_t)(b * 64 + f)) * Ln + l0b + c * 4);
        float a = As[f], c0 = Cs[f];
        v.x = fmaf(v.x, a, c0); v.y = fmaf(v.y, a, c0);
        v.z = fmaf(v.z, a, c0); v.w = fmaf(v.w, a, c0);
        *(float4*)(xns + f * SR + c * 4) = v;
    }
    __syncthreads();
    if (tid < 128) {
        float s1 = 0.f, s2 = 0.f;
#pragma unroll
        for (int f = 0; f < 64; f++) { float t = xns[f * SR + tid]; s1 += t; s2 = fmaf(t, t, s2); }
        float mu = s1 * (1.f / 64.f);
        mus[tid] = mu;
        rss[tid] = rsqrtf(fmaf(-mu, mu, s2 * (1.f / 64.f)) + 1e-5f);
    }
    __syncthreads();

    // thread tile mapping: 4 consecutive e, 8 consecutive l
    int lane = tid & 31, wrp = tid >> 5;
    int eh = wrp & 1, lq = wrp >> 1;
    int le = lane & 7, ll = lane >> 3;
    int e0 = eh * 32 + le * 4;
    int l0 = lq * 32 + ll * 8;
    const float* hb = xns + l0;
    const ull* wbase = (const ull*)wb + e0;
    ull acc[4][4];

    // hoisted LN stats for this thread's 8 l's
    float4 muA = *(const float4*)(mus + l0), muB = *(const float4*)(mus + l0 + 4);
    float4 rsA = *(const float4*)(rss + l0), rsB = *(const float4*)(rss + l0 + 4);
    float muv[8] = {muA.x, muA.y, muA.z, muA.w, muB.x, muB.y, muB.z, muB.w};
    float rsv[8] = {rsA.x, rsA.y, rsA.z, rsA.w, rsB.x, rsB.y, rsB.z, rsB.w};

    // ---- V GEMM ----
    gemm_tile(hb, wbase, acc);
#pragma unroll
    for (int i = 0; i < 4; i++) {
        int e = e0 + i; float dv = dvs[e], cv = cvs[e];
#pragma unroll
        for (int p = 0; p < 4; p++) {
            float2 s = upk(acc[i][p]);
            *(ull*)(vb + e * SR + l0 + 2 * p) = pk2(
                fmaf(rsv[2 * p],     s.x - muv[2 * p] * dv,     cv),
                fmaf(rsv[2 * p + 1], s.y - muv[2 * p + 1] * dv, cv));
        }
    }
    __syncthreads();
    {   // wb <- Wk packed
        const float4* src = (const float4*)g_Wkp;
        float4* dst = (float4*)wb;
#pragma unroll
        for (int i = 0; i < 8; i++) dst[tid + i * 256] = src[tid + i * 256];
    }
    __syncthreads();

    // ---- K GEMM (phi into regs, then overwrite xns) ----
    gemm_tile(hb, wbase, acc);
    ull kreg[4][4];
#pragma unroll
    for (int i = 0; i < 4; i++) {
        int e = e0 + i; float dk = dks[e], ck = cks[e];
#pragma unroll
        for (int p = 0; p < 4; p++) {
            float2 s = upk(acc[i][p]);
            kreg[i][p] = pk2(
                phi_fn(fmaf(rsv[2 * p],     s.x - muv[2 * p] * dk,     ck)),
                phi_fn(fmaf(rsv[2 * p + 1], s.y - muv[2 * p + 1] * dk, ck)));
        }
    }
    __syncthreads();
#pragma unroll
    for (int i = 0; i < 4; i++)
#pragma unroll
        for (int p = 0; p < 4; p++)
            *(ull*)(xns + (e0 + i) * SR + l0 + 2 * p) = kreg[i][p];
    __syncthreads();

    // ---- KV / Z accumulation ----
    if (tid < 128) {
        int hh = tid >> 4;
        int sub = tid & 15;
        int d0 = (sub >> 2) << 1;
        int e2 = (sub & 3) << 1;
        const float* kr0 = xns + (hh * 8 + d0) * SR;
        const float* kr1 = kr0 + SR;
        const float* vr0 = vb + (hh * 8 + e2) * SR;
        const float* vr1 = vr0 + SR;
        ull a00 = 0, a01 = 0, a10 = 0, a11 = 0;
#pragma unroll 4
        for (int j = 0; j < 128; j += 4) {
            ulonglong2 kk0 = *(const ulonglong2*)(kr0 + j);
            ulonglong2 kk1 = *(const ulonglong2*)(kr1 + j);
            ulonglong2 vv0 = *(const ulonglong2*)(vr0 + j);
            ulonglong2 vv1 = *(const ulonglong2*)(vr1 + j);
            fma2(a00, kk0.x, vv0.x); fma2(a00, kk0.y, vv0.y);
            fma2(a01, kk0.x, vv1.x); fma2(a01, kk0.y, vv1.y);
            fma2(a10, kk1.x, vv0.x); fma2(a10, kk1.y, vv0.y);
            fma2(a11, kk1.x, vv1.x); fma2(a11, kk1.y, vv1.y);
        }
        float* kvb = &g_KV[(b * 8 + hh) * 64];
        float2 t;
        t = upk(a00); atomicAdd(kvb + d0 * 8 + e2,           t.x + t.y);
        t = upk(a01); atomicAdd(kvb + d0 * 8 + e2 + 1,       t.x + t.y);
        t = upk(a10); atomicAdd(kvb + (d0 + 1) * 8 + e2,     t.x + t.y);
        t = upk(a11); atomicAdd(kvb + (d0 + 1) * 8 + e2 + 1, t.x + t.y);
    } else if (tid < 192) {
        int r = tid - 128;
        const float* kr = xns + r * SR;
        float s = 0.f;
#pragma unroll
        for (int j = 0; j < 128; j += 4) {
            float4 v = *(const float4*)(kr + j);
            s += (v.x + v.y) + (v.z + v.w);
        }
        atomicAdd(&g_Z[b * 64 + r], s);
    }
}

// ---------------- kernel 3: Q, attention, Wo+residual, fused temporal GEMM ----------------
__global__ void __launch_bounds__(256, 2) k_qo(
    const float* __restrict__ x, const float* __restrict__ gamma, const float* __restrict__ beta,
    const float* __restrict__ bo, const float* __restrict__ Wlin)
{
    extern __shared__ float sm[];
    float*  xns = sm;                          // xn tile; later y tile (stride SRY)
    float*  qb  = sm + 64 * SR;                // q/att tile; later Wlin slab
    float2* wb  = (float2*)(sm + 2 * 64 * SR);
    float*  wls = qb;                          // 96*SRW floats = 12672 <= 16640 available
    __shared__ float mus[128], rss[128], As[64], Cs[64], dqs[64], cqs[64], bos[64];
    __shared__ float KVs[512], Zs[64];

    int b = blockIdx.y, tid = threadIdx.x;
    int l0b = blockIdx.x * 128;

    if (tid < 64) {
        float a = gamma[tid] * g_istd[b * 64 + tid];
        As[tid] = a;
        Cs[tid] = beta[tid] - g_mean[b * 64 + tid] * a;
        dqs[tid] = g_dq[tid]; cqs[tid] = g_cq[tid];
        bos[tid] = bo[tid];
        Zs[tid] = g_Z[b * 64 + tid];
    }
    KVs[tid] = g_KV[b * 512 + tid];
    KVs[tid + 256] = g_KV[b * 512 + 256 + tid];
    {   // wb <- Wq packed
        const float4* src = (const float4*)g_Wqp;
        float4* dst = (float4*)wb;
#pragma unroll
        for (int i = 0; i < 8; i++) dst[tid + i * 256] = src[tid + i * 256];
    }
    __syncthreads();
#pragma unroll
    for (int i = 0; i < 8; i++) {
        int idx = tid + i * 256;
        int f = idx >> 5, c = idx & 31;
        float4 v = *(const float4*)(x + ((size_t)(b * 64 + f)) * Ln + l0b + c * 4);
        float a = As[f], c0 = Cs[f];
        v.x = fmaf(v.x, a, c0); v.y = fmaf(v.y, a, c0);
        v.z = fmaf(v.z, a, c0); v.w = fmaf(v.w, a, c0);
        *(float4*)(xns + f * SR + c * 4) = v;
    }
    __syncthreads();
    if (tid < 128) {
        float s1 = 0.f, s2 = 0.f;
#pragma unroll
        for (int f = 0; f < 64; f++) { float t = xns[f * SR + tid]; s1 += t; s2 = fmaf(t, t, s2); }
        float mu = s1 * (1.f / 64.f);
        mus[tid] = mu;
        rss[tid] = rsqrtf(fmaf(-mu, mu, s2 * (1.f / 64.f)) + 1e-5f);
    }
    __syncthreads();

    int lane = tid & 31, wrp = tid >> 5;
    int eh = wrp & 1, lq = wrp >> 1;
    int le = lane & 7, ll = lane >> 3;
    int e0 = eh * 32 + le * 4;
    int l0 = lq * 32 + ll * 8;
    const ull* wbase = (const ull*)wb + e0;
    ull acc[4][4];

    float4 muA = *(const float4*)(mus + l0), muB = *(const float4*)(mus + l0 + 4);
    float4 rsA = *(const float4*)(rss + l0), rsB = *(const float4*)(rss + l0 + 4);
    float muv[8] = {muA.x, muA.y, muA.z, muA.w, muB.x, muB.y, muB.z, muB.w};
    float rsv[8] = {rsA.x, rsA.y, rsA.z, rsA.w, rsB.x, rsB.y, rsB.z, rsB.w};

    // ---- Q GEMM -> phi -> qb ----
    gemm_tile(xns + l0, wbase, acc);
#pragma unroll
    for (int i = 0; i < 4; i++) {
        int e = e0 + i; float dq = dqs[e], cq = cqs[e];
#pragma unroll
        for (int p = 0; p < 4; p++) {
            float2 s = upk(acc[i][p]);
            *(ull*)(qb + e * SR + l0 + 2 * p) = pk2(
                phi_fn(fmaf(rsv[2 * p],     s.x - muv[2 * p] * dq,     cq)),
                phi_fn(fmaf(rsv[2 * p + 1], s.y - muv[2 * p + 1] * dq, cq)));
        }
    }
    __syncthreads();

    // ---- attention per column ----
    int la = tid >> 1, half = tid & 1;
    float attv[32];
#pragma unroll
    for (int hq = 0; hq < 4; hq++) {
        int hh = half * 4 + hq;
        float q[8];
#pragma unroll
        for (int d = 0; d < 8; d++) q[d] = qb[(hh * 8 + d) * SR + la];
        float nrm = 1e-6f;
#pragma unroll
        for (int d = 0; d < 8; d++) nrm = fmaf(q[d], Zs[hh * 8 + d], nrm);
        float inv = 1.f / nrm;
#pragma unroll
        for (int j = 0; j < 8; j++) {
            float s = 0.f;
#pragma unroll
            for (int d = 0; d < 8; d++) s = fmaf(q[d], KVs[hh * 64 + d * 8 + j], s);
            attv[hq * 8 + j] = s * inv;
        }
    }
    __syncthreads();
#pragma unroll
    for (int i = 0; i < 32; i++)
        qb[(half * 32 + i) * SR + la] = attv[i];
    {   // wb <- WoT packed
        const float4* src = (const float4*)g_Wop;
        float4* dst = (float4*)wb;
#pragma unroll
        for (int i = 0; i < 8; i++) dst[tid + i * 256] = src[tid + i * 256];
    }
    __syncthreads();

    // ---- Wo GEMM + bias + residual -> y (registers) ----
    gemm_tile(qb + l0, (const ull*)wb + e0, acc);
    ull yo[4][4];
#pragma unroll
    for (int i = 0; i < 4; i++) {
        int fo = e0 + i;
        float bb = bos[fo];
        ulonglong2 r01 = *(const ulonglong2*)(xns + fo * SR + l0);
        ulonglong2 r23 = *(const ulonglong2*)(xns + fo * SR + l0 + 4);
        ull rr[4] = {r01.x, r01.y, r23.x, r23.y};
#pragma unroll
        for (int p = 0; p < 4; p++) {
            float2 s = upk(acc[i][p]);
            float2 r = upk(rr[p]);
            yo[i][p] = pk2(s.x + bb + r.x, s.y + bb + r.y);
        }
    }
    __syncthreads();   // everyone done reading xns / qb / wb

    // ---- stage y into xns (stride SRY) and Wlin slab into qb..wb ----
#pragma unroll
    for (int i = 0; i < 4; i++)
#pragma unroll
        for (int p = 0; p < 4; p++)
            *(ull*)(xns + (e0 + i) * SRY + l0 + 2 * p) = yo[i][p];
#pragma unroll
    for (int i = 0; i < 12; i++) {
        int idx = tid + i * 256;               // 3072 = 96 rows x 32 float4
        int p = idx >> 5, c4 = idx & 31;
        float4 v = *(const float4*)(Wlin + (size_t)p * Ln + l0b + c4 * 4);
        *(float4*)(wls + p * SRW + c4 * 4) = v;
    }
    __syncthreads();

    // ---- fused temporal GEMM: M[b,p,f] += sum_l Wlin[p,l] * y[f,l] ----
    int fg = tid & 15, pg = tid >> 4;
    const ull* yb  = (const ull*)xns;   // row stride SRY/2 = 65 ulls
    const ull* wsb = (const ull*)wls;   // row stride SRW/2 = 66 ulls
    ull acc2[6][4];
#pragma unroll
    for (int i = 0; i < 6; i++)
#pragma unroll
        for (int k = 0; k < 4; k++) acc2[i][k] = 0ULL;
#pragma unroll 4
    for (int j = 0; j < 64; j++) {
        ull yv[4], wv[6];
#pragma unroll
        for (int k = 0; k < 4; k++) yv[k] = yb[(fg + 16 * k) * 65 + j];
#pragma unroll
        for (int i = 0; i < 6; i++) wv[i] = wsb[(pg + 16 * i) * 66 + j];
#pragma unroll
        for (int i = 0; i < 6; i++)
#pragma unroll
            for (int k = 0; k < 4; k++) fma2(acc2[i][k], wv[i], yv[k]);
    }
#pragma unroll
    for (int i = 0; i < 6; i++)
#pragma unroll
        for (int k = 0; k < 4; k++) {
            float2 t = upk(acc2[i][k]);
            atomicAdd(&g_M[(b * 96 + pg + 16 * i) * 64 + fg + 16 * k], t.x + t.y);
        }
}

// ---------------- kernel 5: denorm + projector ----------------
__global__ void k_epi(const float* __restrict__ gamma, const float* __restrict__ beta,
                      const float* __restrict__ blin, const float* __restrict__ Wp,
                      const float* __restrict__ bp, float* __restrict__ out) {
    int b = blockIdx.x, p = threadIdx.x;
    float bl = blin[p];
    float s = bp[0];
#pragma unroll
    for (int f = 0; f < 64; f++) {
        float y = g_M[(b * 96 + p) * 64 + f] + bl;
        y = (y - beta[f]) / gamma[f];
        y = fmaf(y, g_stdp[b * 64 + f], g_mean[b * 64 + f]);
        s = fmaf(y, Wp[f], s);
    }
    out[b * 96 + p] = s;
}

// ---------------- launch ----------------
extern "C" void kernel_launch(void* const* d_in, const int* in_sizes, int n_in,
                              void* d_out, int out_size) {
    (void)in_sizes; (void)n_in; (void)out_size;
    const float* x     = (const float*)d_in[0];
    const float* gamma = (const float*)d_in[1];
    const float* beta  = (const float*)d_in[2];
    const float* lnw   = (const float*)d_in[3];
    const float* lnb   = (const float*)d_in[4];
    const float* Wq    = (const float*)d_in[5];
    const float* bq    = (const float*)d_in[6];
    const float* Wk    = (const float*)d_in[7];
    const float* bk    = (const float*)d_in[8];
    const float* Wv    = (const float*)d_in[9];
    const float* bv    = (const float*)d_in[10];
    const float* Wo    = (const float*)d_in[11];
    const float* bo    = (const float*)d_in[12];
    const float* Wlin  = (const float*)d_in[13];
    const float* blin  = (const float*)d_in[14];
    const float* Wp    = (const float*)d_in[15];
    const float* bp    = (const float*)d_in[16];
    float* out = (float*)d_out;

    const int SMB = (2 * 64 * SR + 8192) * 4;   // 100352 bytes dynamic shared
    cudaFuncSetAttribute(k_kv, cudaFuncAttributeMaxDynamicSharedMemorySize, SMB);
    cudaFuncSetAttribute(k_qo, cudaFuncAttributeMaxDynamicSharedMemorySize, SMB);

    k_zero<<<768, 256>>>();
    k_prep<<<1, 256>>>(lnw, lnb, Wq, bq, Wk, bk, Wv, bv, Wo);
    k_stats<<<Bn * Fn, 256>>>(x);
    k_kv<<<dim3(Ln / 128, Bn), 256, SMB>>>(x, gamma, beta);
    k_qo<<<dim3(Ln / 128, Bn), 256, SMB>>>(x, gamma, beta, bo, Wlin);
    k_epi<<<Bn, Pn>>>(gamma, beta, blin, Wp, bp, out);
}

// round 6
// speedup vs baseline: 1.1768x; 1.1768x over previous
#include <cuda_runtime.h>
#include <cstdint>

#define Bn 32
#define Fn 64
#define Ln 8192
#define Pn 96
#define SR 132    // xn/q/v tile row stride (floats)

typedef unsigned long long ull;

// ---------------- scratch (device globals) ----------------
__device__ float g_mean[Bn * Fn];
__device__ float g_istd[Bn * Fn];
__device__ float g_stdp[Bn * Fn];
__device__ float g_KV[Bn * 512];
__device__ float g_Z[Bn * 64];
__device__ float g_M[Bn * Pn * Fn];
// pre-folded, duplicated (f32x2) weights, interleaved layout:
// slot s = j*16 + le*2 + m  <->  e = le*8 + j*2 + m   (row = k = input dim f)
__device__ float2 g_Wqp[4096], g_Wkp[4096], g_Wvp[4096], g_Wop[4096];
__device__ float g_dq[64], g_cq[64], g_dk[64], g_ck[64], g_dv[64], g_cv[64];

// ---------------- helpers ----------------
__device__ __forceinline__ void fma2(ull& d, ull a, ull b) {
    asm("fma.rn.f32x2 %0, %1, %2, %0;" : "+l"(d) : "l"(a), "l"(b));
}
__device__ __forceinline__ float2 upk(ull v) {
    float2 r;
    asm("mov.b64 {%0, %1}, %2;" : "=f"(r.x), "=f"(r.y) : "l"(v));
    return r;
}
__device__ __forceinline__ ull pk2(float a, float b) {
    ull r;
    asm("mov.b64 %0, {%1, %2};" : "=l"(r) : "f"(a), "f"(b));
    return r;
}
__device__ __forceinline__ float phi_fn(float v) {
    return v > 0.f ? v + 1.f : __expf(v);   // elu(x)+1
}

// 64-deep GEMM micro-tile: 8 outputs (e0=le*8) x 8 l (4 f32x2 pairs at l0..l0+7).
// hb = xns + l0 ; wp = wb_ull + le*2. Per k: 2 h-LDS.128 (4 lines, 8-way bcast, 1 wf)
// + 4 w-LDS.128 (8 contiguous 16B lines = 128B, 4-way bcast, 1 wf) = 6 wf / 32 FMA2.
__device__ __forceinline__ void gemm8x8(const float* __restrict__ hb,
                                        const ull* __restrict__ wp,
                                        ull acc[8][4]) {
#pragma unroll
    for (int i = 0; i < 8; i++)
#pragma unroll
        for (int p = 0; p < 4; p++) acc[i][p] = 0ULL;
#pragma unroll 4
    for (int k = 0; k < 64; k++) {
        ulonglong2 hA = *(const ulonglong2*)(hb + k * SR);
        ulonglong2 hB = *(const ulonglong2*)(hb + k * SR + 4);
        ulonglong2 w0 = *(const ulonglong2*)(wp + k * 64);
        ulonglong2 w1 = *(const ulonglong2*)(wp + k * 64 + 16);
        ulonglong2 w2 = *(const ulonglong2*)(wp + k * 64 + 32);
        ulonglong2 w3 = *(const ulonglong2*)(wp + k * 64 + 48);
        ull h[4] = {hA.x, hA.y, hB.x, hB.y};
        ull w[8] = {w0.x, w0.y, w1.x, w1.y, w2.x, w2.y, w3.x, w3.y};
#pragma unroll
        for (int i = 0; i < 8; i++)
#pragma unroll
            for (int p = 0; p < 4; p++) fma2(acc[i][p], w[i], h[p]);
    }
}

// ---------------- kernel 0: zero accumulators ----------------
__global__ void k_zero() {
    int i = blockIdx.x * blockDim.x + threadIdx.x;
    if (i < Bn * 512)      g_KV[i] = 0.f;
    if (i < Bn * 64)       g_Z[i]  = 0.f;
    if (i < Bn * Pn * Fn)  g_M[i]  = 0.f;
}

// ---------------- prep: fold LN into weights, duplicate + interleave ----------------
__global__ void __launch_bounds__(256) k_prep(
    const float* __restrict__ lnw, const float* __restrict__ lnb,
    const float* __restrict__ Wq, const float* __restrict__ bq,
    const float* __restrict__ Wk, const float* __restrict__ bk,
    const float* __restrict__ Wv, const float* __restrict__ bv,
    const float* __restrict__ Wo)
{
    int tid = threadIdx.x;
#pragma unroll
    for (int i = 0; i < 16; i++) {
        int idx = tid + i * 256;          // idx = f*64 + s
        int f = idx >> 6, s = idx & 63;
        int j = s >> 4, r = s & 15, le = r >> 1, m = r & 1;
        int e = le * 8 + j * 2 + m;
        float lw = lnw[f];
        float wq = Wq[e * 64 + f] * lw;  g_Wqp[idx] = make_float2(wq, wq);
        float wk = Wk[e * 64 + f] * lw;  g_Wkp[idx] = make_float2(wk, wk);
        float wv = Wv[e * 64 + f] * lw;  g_Wvp[idx] = make_float2(wv, wv);
        float wo = Wo[e * 64 + f];       g_Wop[idx] = make_float2(wo, wo);  // WoT[k=e_att][fo]
    }
    if (tid < 64) {
        int e = tid;
        float dq = 0.f, cq = 0.f, dk = 0.f, ck = 0.f, dv = 0.f, cv = 0.f;
        for (int f = 0; f < 64; f++) {
            float lw = lnw[f], lb2 = lnb[f];
            float wq = Wq[e * 64 + f], wk = Wk[e * 64 + f], wv = Wv[e * 64 + f];
            dq += wq * lw;  cq = fmaf(lb2, wq, cq);
            dk += wk * lw;  ck = fmaf(lb2, wk, ck);
            dv += wv * lw;  cv = fmaf(lb2, wv, cv);
        }
        g_dq[e] = dq; g_cq[e] = cq + bq[e];
        g_dk[e] = dk; g_ck[e] = ck + bk[e];
        g_dv[e] = dv; g_cv[e] = cv + bv[e];
    }
}

// ---------------- kernel 1: RevIN stats per (b,f) ----------------
__global__ void __launch_bounds__(256) k_stats(const float* __restrict__ x) {
    int bf = blockIdx.x;
    const float4* p = (const float4*)(x + (size_t)bf * Ln);
    float s1 = 0.f, s2 = 0.f;
    for (int i = threadIdx.x; i < Ln / 4; i += 256) {
        float4 v = p[i];
        s1 += (v.x + v.y) + (v.z + v.w);
        s2 = fmaf(v.x, v.x, s2); s2 = fmaf(v.y, v.y, s2);
        s2 = fmaf(v.z, v.z, s2); s2 = fmaf(v.w, v.w, s2);
    }
    __shared__ float r1[256], r2[256];
    r1[threadIdx.x] = s1; r2[threadIdx.x] = s2;
    __syncthreads();
    for (int s = 128; s > 0; s >>= 1) {
        if (threadIdx.x < s) {
            r1[threadIdx.x] += r1[threadIdx.x + s];
            r2[threadIdx.x] += r2[threadIdx.x + s];
        }
        __syncthreads();
    }
    if (threadIdx.x == 0) {
        float S1 = r1[0], S2 = r2[0];
        float mean = S1 / (float)Ln;
        float var = (S2 - S1 * mean) / (float)(Ln - 1);
        var = fmaxf(var, 0.f);
        float stdp = sqrtf(var) + 1e-5f;
        g_mean[bf] = mean; g_stdp[bf] = stdp; g_istd[bf] = 1.f / stdp;
    }
}

// ---------------- kernel 2: K/V projections + KV,Z (128 threads) ----------------
__global__ void __launch_bounds__(128) k_kv(
    const float* __restrict__ x, const float* __restrict__ gamma, const float* __restrict__ beta)
{
    extern __shared__ float sm[];
    float* xns = sm;                         // 64*SR; later phi(K)
    float* vb  = sm + 64 * SR;               // 64*SR
    ull*   wb  = (ull*)(sm + 2 * 64 * SR);   // 4096 ulls
    __shared__ float mus[128], rss[128], As[64], Cs[64];
    __shared__ float dks[64], cks[64], dvs[64], cvs[64];

    int b = blockIdx.y, tid = threadIdx.x;
    int l0b = blockIdx.x * 128;

    if (tid < 64) {
        float a = gamma[tid] * g_istd[b * 64 + tid];
        As[tid] = a;
        Cs[tid] = beta[tid] - g_mean[b * 64 + tid] * a;
        dks[tid] = g_dk[tid]; cks[tid] = g_ck[tid];
        dvs[tid] = g_dv[tid]; cvs[tid] = g_cv[tid];
    }
    {   // wb <- Wv
        const float4* src = (const float4*)g_Wvp;
        float4* dst = (float4*)wb;
#pragma unroll
        for (int i = 0; i < 16; i++) dst[tid + i * 128] = src[tid + i * 128];
    }
    __syncthreads();
#pragma unroll
    for (int i = 0; i < 16; i++) {
        int idx = tid + i * 128;
        int f = idx >> 5, c = idx & 31;
        float4 v = *(const float4*)(x + ((size_t)(b * 64 + f)) * Ln + l0b + c * 4);
        float a = As[f], c0 = Cs[f];
        v.x = fmaf(v.x, a, c0); v.y = fmaf(v.y, a, c0);
        v.z = fmaf(v.z, a, c0); v.w = fmaf(v.w, a, c0);
        *(float4*)(xns + f * SR + c * 4) = v;
    }
    __syncthreads();
    {   // LN stats, one column per thread
        float s1 = 0.f, s2 = 0.f;
#pragma unroll
        for (int f = 0; f < 64; f++) { float t = xns[f * SR + tid]; s1 += t; s2 = fmaf(t, t, s2); }
        float mu = s1 * (1.f / 64.f);
        mus[tid] = mu;
        rss[tid] = rsqrtf(fmaf(-mu, mu, s2 * (1.f / 64.f)) + 1e-5f);
    }
    __syncthreads();

    int lane = tid & 31, wi = tid >> 5;
    int le = lane & 7, lsub = lane >> 3;
    int e0 = le * 8;
    int l0 = wi * 32 + lsub * 8;
    const ull* wp = wb + le * 2;
    ull acc[8][4];

    float4 muA = *(const float4*)(mus + l0), muB = *(const float4*)(mus + l0 + 4);
    float4 rsA = *(const float4*)(rss + l0), rsB = *(const float4*)(rss + l0 + 4);
    float muv[8] = {muA.x, muA.y, muA.z, muA.w, muB.x, muB.y, muB.z, muB.w};
    float rsv[8] = {rsA.x, rsA.y, rsA.z, rsA.w, rsB.x, rsB.y, rsB.z, rsB.w};

    // ---- V GEMM + epilogue -> vb ----
    gemm8x8(xns + l0, wp, acc);
#pragma unroll
    for (int i = 0; i < 8; i++) {
        int e = e0 + i; float dv = dvs[e], cv = cvs[e];
        ull t[4];
#pragma unroll
        for (int p = 0; p < 4; p++) {
            float2 s = upk(acc[i][p]);
            t[p] = pk2(fmaf(rsv[2 * p],     s.x - muv[2 * p] * dv,     cv),
                       fmaf(rsv[2 * p + 1], s.y - muv[2 * p + 1] * dv, cv));
        }
        *(ulonglong2*)(vb + e * SR + l0)     = make_ulonglong2(t[0], t[1]);
        *(ulonglong2*)(vb + e * SR + l0 + 4) = make_ulonglong2(t[2], t[3]);
    }
    __syncthreads();
    {   // wb <- Wk
        const float4* src = (const float4*)g_Wkp;
        float4* dst = (float4*)wb;
#pragma unroll
        for (int i = 0; i < 16; i++) dst[tid + i * 128] = src[tid + i * 128];
    }
    __syncthreads();

    // ---- K GEMM, phi in place ----
    gemm8x8(xns + l0, wp, acc);
#pragma unroll
    for (int i = 0; i < 8; i++) {
        int e = e0 + i; float dk = dks[e], ck = cks[e];
#pragma unroll
        for (int p = 0; p < 4; p++) {
            float2 s = upk(acc[i][p]);
            acc[i][p] = pk2(phi_fn(fmaf(rsv[2 * p],     s.x - muv[2 * p] * dk,     ck)),
                            phi_fn(fmaf(rsv[2 * p + 1], s.y - muv[2 * p + 1] * dk, ck)));
        }
    }
    __syncthreads();   // all GEMM reads of xns done
#pragma unroll
    for (int i = 0; i < 8; i++) {
        *(ulonglong2*)(xns + (e0 + i) * SR + l0)     = make_ulonglong2(acc[i][0], acc[i][1]);
        *(ulonglong2*)(xns + (e0 + i) * SR + l0 + 4) = make_ulonglong2(acc[i][2], acc[i][3]);
    }
    __syncthreads();

    // ---- KV accumulation (all 128 threads) ----
    {
        int hh = tid >> 4;
        int sub = tid & 15;
        int d0 = (sub >> 2) << 1;
        int e2 = (sub & 3) << 1;
        const float* kr0 = xns + (hh * 8 + d0) * SR;
        const float* kr1 = kr0 + SR;
        const float* vr0 = vb + (hh * 8 + e2) * SR;
        const float* vr1 = vr0 + SR;
        ull a00 = 0, a01 = 0, a10 = 0, a11 = 0;
#pragma unroll 4
        for (int j = 0; j < 128; j += 4) {
            ulonglong2 kk0 = *(const ulonglong2*)(kr0 + j);
            ulonglong2 kk1 = *(const ulonglong2*)(kr1 + j);
            ulonglong2 vv0 = *(const ulonglong2*)(vr0 + j);
            ulonglong2 vv1 = *(const ulonglong2*)(vr1 + j);
            fma2(a00, kk0.x, vv0.x); fma2(a00, kk0.y, vv0.y);
            fma2(a01, kk0.x, vv1.x); fma2(a01, kk0.y, vv1.y);
            fma2(a10, kk1.x, vv0.x); fma2(a10, kk1.y, vv0.y);
            fma2(a11, kk1.x, vv1.x); fma2(a11, kk1.y, vv1.y);
        }
        float* kvb = &g_KV[(b * 8 + hh) * 64];
        float2 t;
        t = upk(a00); atomicAdd(kvb + d0 * 8 + e2,           t.x + t.y);
        t = upk(a01); atomicAdd(kvb + d0 * 8 + e2 + 1,       t.x + t.y);
        t = upk(a10); atomicAdd(kvb + (d0 + 1) * 8 + e2,     t.x + t.y);
        t = upk(a11); atomicAdd(kvb + (d0 + 1) * 8 + e2 + 1, t.x + t.y);
    }
    // ---- Z (first 64 threads) ----
    if (tid < 64) {
        const float* kr = xns + tid * SR;
        float s = 0.f;
#pragma unroll
        for (int j = 0; j < 128; j += 4) {
            float4 v = *(const float4*)(kr + j);
            s += (v.x + v.y) + (v.z + v.w);
        }
        atomicAdd(&g_Z[b * 64 + tid], s);
    }
}

// ---------------- kernel 3: Q, attention, Wo+residual, fused temporal GEMM ----------------
__global__ void __launch_bounds__(128) k_qo(
    const float* __restrict__ x, const float* __restrict__ gamma, const float* __restrict__ beta,
    const float* __restrict__ bo, const float* __restrict__ Wlin)
{
    extern __shared__ float sm[];
    float* xns  = sm;                         // xn tile; later start of Wlin slab
    float* qb   = sm + 64 * SR;               // q / att tile
    ull*   wbig = (ull*)(sm + 2 * 64 * SR);   // Wq / WoT (64x64 ull); later y at 65-ull stride
    ull*   wls  = (ull*)sm;                   // Wlin slab: 96 rows x 64 ulls, contiguous
    __shared__ float mus[128], rss[128], As[64], Cs[64], dqs[64], cqs[64], bos[64];
    __shared__ float KVs[512], Zs[64];

    int b = blockIdx.y, tid = threadIdx.x;
    int l0b = blockIdx.x * 128;

    if (tid < 64) {
        float a = gamma[tid] * g_istd[b * 64 + tid];
        As[tid] = a;
        Cs[tid] = beta[tid] - g_mean[b * 64 + tid] * a;
        dqs[tid] = g_dq[tid]; cqs[tid] = g_cq[tid];
        bos[tid] = bo[tid];
        Zs[tid] = g_Z[b * 64 + tid];
    }
#pragma unroll
    for (int i = 0; i < 4; i++) KVs[tid + i * 128] = g_KV[b * 512 + tid + i * 128];
    {   // wbig <- Wq
        const float4* src = (const float4*)g_Wqp;
        float4* dst = (float4*)wbig;
#pragma unroll
        for (int i = 0; i < 16; i++) dst[tid + i * 128] = src[tid + i * 128];
    }
    __syncthreads();
#pragma unroll
    for (int i = 0; i < 16; i++) {
        int idx = tid + i * 128;
        int f = idx >> 5, c = idx & 31;
        float4 v = *(const float4*)(x + ((size_t)(b * 64 + f)) * Ln + l0b + c * 4);
        float a = As[f], c0 = Cs[f];
        v.x = fmaf(v.x, a, c0); v.y = fmaf(v.y, a, c0);
        v.z = fmaf(v.z, a, c0); v.w = fmaf(v.w, a, c0);
        *(float4*)(xns + f * SR + c * 4) = v;
    }
    __syncthreads();
    {
        float s1 = 0.f, s2 = 0.f;
#pragma unroll
        for (int f = 0; f < 64; f++) { float t = xns[f * SR + tid]; s1 += t; s2 = fmaf(t, t, s2); }
        float mu = s1 * (1.f / 64.f);
        mus[tid] = mu;
        rss[tid] = rsqrtf(fmaf(-mu, mu, s2 * (1.f / 64.f)) + 1e-5f);
    }
    __syncthreads();

    int lane = tid & 31, wi = tid >> 5;
    int le = lane & 7, lsub = lane >> 3;
    int e0 = le * 8;
    int l0 = wi * 32 + lsub * 8;
    ull acc[8][4];

    float4 muA = *(const float4*)(mus + l0), muB = *(const float4*)(mus + l0 + 4);
    float4 rsA = *(const float4*)(rss + l0), rsB = *(const float4*)(rss + l0 + 4);
    float muv[8] = {muA.x, muA.y, muA.z, muA.w, muB.x, muB.y, muB.z, muB.w};
    float rsv[8] = {rsA.x, rsA.y, rsA.z, rsA.w, rsB.x, rsB.y, rsB.z, rsB.w};

    // ---- Q GEMM -> phi -> qb ----
    gemm8x8(xns + l0, wbig + le * 2, acc);
#pragma unroll
    for (int i = 0; i < 8; i++) {
        int e = e0 + i; float dq = dqs[e], cq = cqs[e];
        ull t[4];
#pragma unroll
        for (int p = 0; p < 4; p++) {
            float2 s = upk(acc[i][p]);
            t[p] = pk2(phi_fn(fmaf(rsv[2 * p],     s.x - muv[2 * p] * dq,     cq)),
                       phi_fn(fmaf(rsv[2 * p + 1], s.y - muv[2 * p + 1] * dq, cq)));
        }
        *(ulonglong2*)(qb + e * SR + l0)     = make_ulonglong2(t[0], t[1]);
        *(ulonglong2*)(qb + e * SR + l0 + 4) = make_ulonglong2(t[2], t[3]);
    }
    __syncthreads();   // q complete; Wq reads done

    // ---- reload wbig <- WoT, and attention on own column la = tid ----
    {
        const float4* src = (const float4*)g_Wop;
        float4* dst = (float4*)wbig;
#pragma unroll
        for (int i = 0; i < 16; i++) dst[tid + i * 128] = src[tid + i * 128];
    }
    {
        int la = tid;
#pragma unroll
        for (int hh = 0; hh < 8; hh++) {
            float q[8];
#pragma unroll
            for (int d = 0; d < 8; d++) q[d] = qb[(hh * 8 + d) * SR + la];
            float nrm = 1e-6f;
#pragma unroll
            for (int d = 0; d < 8; d++) nrm = fmaf(q[d], Zs[hh * 8 + d], nrm);
            float inv = 1.f / nrm;
#pragma unroll
            for (int j = 0; j < 8; j++) {
                float s = 0.f;
#pragma unroll
                for (int d = 0; d < 8; d++) s = fmaf(q[d], KVs[hh * 64 + d * 8 + j], s);
                qb[(hh * 8 + j) * SR + la] = s * inv;   // own column: no race
            }
        }
    }
    __syncthreads();

    // ---- Wo GEMM + bias + residual -> y in wbig (65-ull row stride) ----
    gemm8x8(qb + l0, wbig + le * 2, acc);
    __syncthreads();   // all WoT reads done before overwriting wbig
#pragma unroll
    for (int i = 0; i < 8; i++) {
        int fo = e0 + i;
        float bb = bos[fo];
        ulonglong2 r01 = *(const ulonglong2*)(xns + fo * SR + l0);
        ulonglong2 r23 = *(const ulonglong2*)(xns + fo * SR + l0 + 4);
        ull rr[4] = {r01.x, r01.y, r23.x, r23.y};
#pragma unroll
        for (int p = 0; p < 4; p++) {
            float2 s = upk(acc[i][p]);
            float2 r = upk(rr[p]);
            wbig[fo * 65 + l0 / 2 + p] = pk2(s.x + bb + r.x, s.y + bb + r.y);
        }
    }
    __syncthreads();   // residual reads done; y complete

    // ---- Wlin slab (96 x 64 ulls, contiguous) into xns/qb space ----
#pragma unroll
    for (int i = 0; i < 24; i++) {
        int idx = tid + i * 128;               // 3072 float4 = 96 rows x 32
        int p = idx >> 5, c4 = idx & 31;
        ((float4*)wls)[(p << 5) + c4] = *(const float4*)(Wlin + (size_t)p * Ln + l0b + c4 * 4);
    }
    __syncthreads();

    // ---- temporal GEMM: M[b,p,f] += sum_l Wlin[p,l] * y[f,l] ----
    int fg = tid & 15, pg = tid >> 4;          // 16 f-groups x 8 p-groups
    ull acc2[12][4];
#pragma unroll
    for (int i = 0; i < 12; i++)
#pragma unroll
        for (int k = 0; k < 4; k++) acc2[i][k] = 0ULL;
#pragma unroll 4
    for (int j = 0; j < 64; j++) {
        ull yv[4], wv[12];
#pragma unroll
        for (int k = 0; k < 4; k++) yv[k] = wbig[(fg + 16 * k) * 65 + j];
#pragma unroll
        for (int i = 0; i < 12; i++) wv[i] = wls[(pg + 8 * i) * 64 + j];
#pragma unroll
        for (int i = 0; i < 12; i++)
#pragma unroll
            for (int k = 0; k < 4; k++) fma2(acc2[i][k], wv[i], yv[k]);
    }
#pragma unroll
    for (int i = 0; i < 12; i++)
#pragma unroll
        for (int k = 0; k < 4; k++) {
            float2 t = upk(acc2[i][k]);
            atomicAdd(&g_M[(b * 96 + pg + 8 * i) * 64 + fg + 16 * k], t.x + t.y);
        }
}

// ---------------- kernel 5: denorm + projector ----------------
__global__ void k_epi(const float* __restrict__ gamma, const float* __restrict__ beta,
                      const float* __restrict__ blin, const float* __restrict__ Wp,
                      const float* __restrict__ bp, float* __restrict__ out) {
    int b = blockIdx.x, p = threadIdx.x;
    float bl = blin[p];
    float s = bp[0];
#pragma unroll
    for (int f = 0; f < 64; f++) {
        float y = g_M[(b * 96 + p) * 64 + f] + bl;
        y = (y - beta[f]) / gamma[f];
        y = fmaf(y, g_stdp[b * 64 + f], g_mean[b * 64 + f]);
        s = fmaf(y, Wp[f], s);
    }
    out[b * 96 + p] = s;
}

// ---------------- launch ----------------
extern "C" void kernel_launch(void* const* d_in, const int* in_sizes, int n_in,
                              void* d_out, int out_size) {
    (void)in_sizes; (void)n_in; (void)out_size;
    const float* x     = (const float*)d_in[0];
    const float* gamma = (const float*)d_in[1];
    const float* beta  = (const float*)d_in[2];
    const float* lnw   = (const float*)d_in[3];
    const float* lnb   = (const float*)d_in[4];
    const float* Wq    = (const float*)d_in[5];
    const float* bq    = (const float*)d_in[6];
    const float* Wk    = (const float*)d_in[7];
    const float* bk    = (const float*)d_in[8];
    const float* Wv    = (const float*)d_in[9];
    const float* bv    = (const float*)d_in[10];
    const float* Wo    = (const float*)d_in[11];
    const float* bo    = (const float*)d_in[12];
    const float* Wlin  = (const float*)d_in[13];
    const float* blin  = (const float*)d_in[14];
    const float* Wp    = (const float*)d_in[15];
    const float* bp    = (const float*)d_in[16];
    float* out = (float*)d_out;

    const int SMB = 2 * 64 * SR * 4 + 64 * 65 * 8;   // 67584 + 33280 = 100864 bytes
    cudaFuncSetAttribute(k_kv, cudaFuncAttributeMaxDynamicSharedMemorySize, SMB);
    cudaFuncSetAttribute(k_qo, cudaFuncAttributeMaxDynamicSharedMemorySize, SMB);

    k_zero<<<768, 256>>>();
    k_prep<<<1, 256>>>(lnw, lnb, Wq, bq, Wk, bk, Wv, bv, Wo);
    k_stats<<<Bn * Fn, 256>>>(x);
    k_kv<<<dim3(Ln / 128, Bn), 128, SMB>>>(x, gamma, beta);
    k_qo<<<dim3(Ln / 128, Bn), 128, SMB>>>(x, gamma, beta, bo, Wlin);
    k_epi<<<Bn, Pn>>>(gamma, beta, blin, Wp, bp, out);
}

// round 7
// speedup vs baseline: 1.3446x; 1.1425x over previous
#include <cuda_runtime.h>
#include <cstdint>

#define Bn 32
#define Fn 64
#define Ln 8192
#define Pn 96
#define SR 132    // data tile row stride (floats)

typedef unsigned long long ull;

// ---------------- scratch (device globals) ----------------
__device__ float g_mean[Bn * Fn];
__device__ float g_istd[Bn * Fn];
__device__ float g_stdp[Bn * Fn];
__device__ float g_KV[Bn * 512];
__device__ float g_Z[Bn * 64];
__device__ float g_M[Bn * Pn * Fn];
// pre-folded plain-float weights, layout [k(=input dim)][e(=output dim)]
__device__ float g_Wqf[4096], g_Wkf[4096], g_Wvf[4096], g_Wof[4096];
__device__ float g_dq[64], g_cq[64], g_dk[64], g_ck[64], g_dv[64], g_cv[64];

// ---------------- helpers ----------------
__device__ __forceinline__ void fma2(ull& d, ull a, ull b) {
    asm("fma.rn.f32x2 %0, %1, %2, %0;" : "+l"(d) : "l"(a), "l"(b));
}
__device__ __forceinline__ float2 upk(ull v) {
    float2 r;
    asm("mov.b64 {%0, %1}, %2;" : "=f"(r.x), "=f"(r.y) : "l"(v));
    return r;
}
__device__ __forceinline__ ull pk2(float a, float b) {
    ull r;
    asm("mov.b64 %0, {%1, %2};" : "=l"(r) : "f"(a), "f"(b));
    return r;
}
__device__ __forceinline__ ull dup(float a) { return pk2(a, a); }
__device__ __forceinline__ float phi_fn(float v) {
    return v > 0.f ? v + 1.f : __expf(v);   // elu(x)+1
}

// ---------------- kernel 0: zero accumulators ----------------
__global__ void k_zero() {
    int i = blockIdx.x * blockDim.x + threadIdx.x;
    if (i < Bn * 512)      g_KV[i] = 0.f;
    if (i < Bn * 64)       g_Z[i]  = 0.f;
    if (i < Bn * Pn * Fn)  g_M[i]  = 0.f;
}

// ---------------- prep: fold LN into weights ----------------
__global__ void __launch_bounds__(256) k_prep(
    const float* __restrict__ lnw, const float* __restrict__ lnb,
    const float* __restrict__ Wq, const float* __restrict__ bq,
    const float* __restrict__ Wk, const float* __restrict__ bk,
    const float* __restrict__ Wv, const float* __restrict__ bv,
    const float* __restrict__ Wo)
{
    int tid = threadIdx.x;
#pragma unroll
    for (int i = 0; i < 16; i++) {
        int idx = tid + i * 256;          // idx = f*64 + e  (f = k/reduction dim)
        int f = idx >> 6, e = idx & 63;
        float lw = lnw[f];
        g_Wqf[idx] = Wq[e * 64 + f] * lw;
        g_Wkf[idx] = Wk[e * 64 + f] * lw;
        g_Wvf[idx] = Wv[e * 64 + f] * lw;
        g_Wof[idx] = Wo[e * 64 + f];      // WoT[k=e_att][fo]
    }
    if (tid < 64) {
        int e = tid;
        float dq = 0.f, cq = 0.f, dk = 0.f, ck = 0.f, dv = 0.f, cv = 0.f;
        for (int f = 0; f < 64; f++) {
            float lw = lnw[f], lb2 = lnb[f];
            float wq = Wq[e * 64 + f], wk = Wk[e * 64 + f], wv = Wv[e * 64 + f];
            dq += wq * lw;  cq = fmaf(lb2, wq, cq);
            dk += wk * lw;  ck = fmaf(lb2, wk, ck);
            dv += wv * lw;  cv = fmaf(lb2, wv, cv);
        }
        g_dq[e] = dq; g_cq[e] = cq + bq[e];
        g_dk[e] = dk; g_ck[e] = ck + bk[e];
        g_dv[e] = dv; g_cv[e] = cv + bv[e];
    }
}

// ---------------- kernel 1: RevIN stats per (b,f) ----------------
__global__ void __launch_bounds__(256) k_stats(const float* __restrict__ x) {
    int bf = blockIdx.x;
    const float4* p = (const float4*)(x + (size_t)bf * Ln);
    float s1 = 0.f, s2 = 0.f;
    for (int i = threadIdx.x; i < Ln / 4; i += 256) {
        float4 v = p[i];
        s1 += (v.x + v.y) + (v.z + v.w);
        s2 = fmaf(v.x, v.x, s2); s2 = fmaf(v.y, v.y, s2);
        s2 = fmaf(v.z, v.z, s2); s2 = fmaf(v.w, v.w, s2);
    }
    __shared__ float r1[256], r2[256];
    r1[threadIdx.x] = s1; r2[threadIdx.x] = s2;
    __syncthreads();
    for (int s = 128; s > 0; s >>= 1) {
        if (threadIdx.x < s) {
            r1[threadIdx.x] += r1[threadIdx.x + s];
            r2[threadIdx.x] += r2[threadIdx.x + s];
        }
        __syncthreads();
    }
    if (threadIdx.x == 0) {
        float S1 = r1[0], S2 = r2[0];
        float mean = S1 / (float)Ln;
        float var = (S2 - S1 * mean) / (float)(Ln - 1);
        var = fmaxf(var, 0.f);
        float stdp = sqrtf(var) + 1e-5f;
        g_mean[bf] = mean; g_stdp[bf] = stdp; g_istd[bf] = 1.f / stdp;
    }
}

// ---------------- kernel 2: fused K+V projections + KV,Z (512 threads) ----------------
__global__ void __launch_bounds__(512) k_kv(
    const float* __restrict__ x, const float* __restrict__ gamma, const float* __restrict__ beta)
{
    extern __shared__ float sm[];
    float* xns = sm;                     // 64*SR floats; later phi(K)
    float* vb  = sm + 64 * SR;           // 64*SR floats
    float* wv  = sm + 2 * 64 * SR;       // 4096 floats
    float* wk  = wv + 4096;              // 4096 floats
    __shared__ float mus[128], rss[128], As[64], Cs[64];
    __shared__ float dks[64], cks[64], dvs[64], cvs[64];

    int b = blockIdx.y, tid = threadIdx.x;
    int l0b = blockIdx.x * 128;

    if (tid < 64) {
        float a = gamma[tid] * g_istd[b * 64 + tid];
        As[tid] = a;
        Cs[tid] = beta[tid] - g_mean[b * 64 + tid] * a;
        dks[tid] = g_dk[tid]; cks[tid] = g_ck[tid];
        dvs[tid] = g_dv[tid]; cvs[tid] = g_cv[tid];
    }
#pragma unroll
    for (int i = 0; i < 2; i++) {
        ((float4*)wv)[tid + i * 512] = ((const float4*)g_Wvf)[tid + i * 512];
        ((float4*)wk)[tid + i * 512] = ((const float4*)g_Wkf)[tid + i * 512];
    }
    __syncthreads();
#pragma unroll
    for (int i = 0; i < 4; i++) {
        int idx = tid + i * 512;
        int f = idx >> 5, c = idx & 31;
        float4 v = *(const float4*)(x + ((size_t)(b * 64 + f)) * Ln + l0b + c * 4);
        float a = As[f], c0 = Cs[f];
        v.x = fmaf(v.x, a, c0); v.y = fmaf(v.y, a, c0);
        v.z = fmaf(v.z, a, c0); v.w = fmaf(v.w, a, c0);
        *(float4*)(xns + f * SR + c * 4) = v;
    }
    __syncthreads();
    if (tid < 128) {
        float s1 = 0.f, s2 = 0.f;
#pragma unroll
        for (int f = 0; f < 64; f++) { float t = xns[f * SR + tid]; s1 += t; s2 = fmaf(t, t, s2); }
        float mu = s1 * (1.f / 64.f);
        mus[tid] = mu;
        rss[tid] = rsqrtf(fmaf(-mu, mu, s2 * (1.f / 64.f)) + 1e-5f);
    }
    __syncthreads();

    // mapping: pglow = tid&15, eg = (tid>>4)&15, pghi = tid>>8
    // thread: e = eg*4..+3 ; l-pairs at l = 2*pg and 2*pg+64, pg = pglow+16*pghi
    int pg = (tid & 15) + 16 * (tid >> 8);
    int eg = (tid >> 4) & 15;
    int e0 = eg * 4;
    const float* hb = xns + 2 * pg;
    const float* wvp = wv + e0;
    const float* wkp = wk + e0;

    ull aV[4][2], aK[4][2];
#pragma unroll
    for (int i = 0; i < 4; i++) { aV[i][0] = aV[i][1] = aK[i][0] = aK[i][1] = 0ULL; }
#pragma unroll 8
    for (int k = 0; k < 64; k++) {
        ull h0 = *(const ull*)(hb + k * SR);
        ull h1 = *(const ull*)(hb + k * SR + 64);
        float4 v4 = *(const float4*)(wvp + k * 64);
        float4 k4 = *(const float4*)(wkp + k * 64);
        ull wvd[4] = {dup(v4.x), dup(v4.y), dup(v4.z), dup(v4.w)};
        ull wkd[4] = {dup(k4.x), dup(k4.y), dup(k4.z), dup(k4.w)};
#pragma unroll
        for (int i = 0; i < 4; i++) {
            fma2(aV[i][0], wvd[i], h0); fma2(aV[i][1], wvd[i], h1);
            fma2(aK[i][0], wkd[i], h0); fma2(aK[i][1], wkd[i], h1);
        }
    }

    // hoisted LN stats for this thread's 4 l's
    float2 mu0 = upk(*(const ull*)(mus + 2 * pg));
    float2 mu1 = upk(*(const ull*)(mus + 2 * pg + 64));
    float2 rs0 = upk(*(const ull*)(rss + 2 * pg));
    float2 rs1 = upk(*(const ull*)(rss + 2 * pg + 64));

    // ---- V epilogue -> vb (no sync needed: vb not read during GEMM) ----
#pragma unroll
    for (int i = 0; i < 4; i++) {
        int e = e0 + i; float dv = dvs[e], cv = cvs[e];
        float2 s0 = upk(aV[i][0]), s1 = upk(aV[i][1]);
        *(ull*)(vb + e * SR + 2 * pg) =
            pk2(fmaf(rs0.x, s0.x - mu0.x * dv, cv), fmaf(rs0.y, s0.y - mu0.y * dv, cv));
        *(ull*)(vb + e * SR + 2 * pg + 64) =
            pk2(fmaf(rs1.x, s1.x - mu1.x * dv, cv), fmaf(rs1.y, s1.y - mu1.y * dv, cv));
    }
    // ---- K epilogue: phi in regs ----
    ull kw[4][2];
#pragma unroll
    for (int i = 0; i < 4; i++) {
        int e = e0 + i; float dk = dks[e], ck = cks[e];
        float2 s0 = upk(aK[i][0]), s1 = upk(aK[i][1]);
        kw[i][0] = pk2(phi_fn(fmaf(rs0.x, s0.x - mu0.x * dk, ck)),
                       phi_fn(fmaf(rs0.y, s0.y - mu0.y * dk, ck)));
        kw[i][1] = pk2(phi_fn(fmaf(rs1.x, s1.x - mu1.x * dk, ck)),
                       phi_fn(fmaf(rs1.y, s1.y - mu1.y * dk, ck)));
    }
    __syncthreads();   // all GEMM reads of xns done
#pragma unroll
    for (int i = 0; i < 4; i++) {
        *(ull*)(xns + (e0 + i) * SR + 2 * pg)      = kw[i][0];
        *(ull*)(xns + (e0 + i) * SR + 2 * pg + 64) = kw[i][1];
    }
    __syncthreads();

    // ---- KV accumulation: one (hh,d,e) entry per thread ----
    {
        int hh = tid >> 6;
        int d  = (tid >> 3) & 7;
        int e2 = tid & 7;
        const float* kr = xns + (hh * 8 + d) * SR;
        const float* vr = vb + (hh * 8 + e2) * SR;
        ull a = 0ULL;
#pragma unroll 8
        for (int j = 0; j < 128; j += 4) {
            ulonglong2 kk = *(const ulonglong2*)(kr + j);
            ulonglong2 vv = *(const ulonglong2*)(vr + j);
            fma2(a, kk.x, vv.x);
            fma2(a, kk.y, vv.y);
        }
        float2 t = upk(a);
        atomicAdd(&g_KV[(b * 8 + hh) * 64 + d * 8 + e2], t.x + t.y);
    }
    if (tid < 64) {
        const float* kr = xns + tid * SR;
        float s = 0.f;
#pragma unroll
        for (int j = 0; j < 128; j += 4) {
            float4 v = *(const float4*)(kr + j);
            s += (v.x + v.y) + (v.z + v.w);
        }
        atomicAdd(&g_Z[b * 64 + tid], s);
    }
}

// ---------------- kernel 3: Q, attention, Wo+residual, fused temporal (512 threads) ----------------
__global__ void __launch_bounds__(512) k_qo(
    const float* __restrict__ x, const float* __restrict__ gamma, const float* __restrict__ beta,
    const float* __restrict__ bo, const float* __restrict__ Wlin)
{
    extern __shared__ float sm[];
    float* wq  = sm;                    // 4096 floats (Wq, then WoT)
    float* xns = sm + 4096;             // 64*SR
    float* qb  = sm + 4096 + 64 * SR;   // 64*SR; later y tile (66-ull row stride)
    ull*   wy  = (ull*)qb;              // y: 64 rows x 66 ulls = 33792 B (fits exactly)
    ull*   wlu = (ull*)sm;              // Wlin slab: 96 rows x 64 ulls = 49152 B over wq+xns
    __shared__ float mus[128], rss[128], As[64], Cs[64], dqs[64], cqs[64], bos[64];
    __shared__ float KVs[512], Zs[64];

    int b = blockIdx.y, tid = threadIdx.x;
    int l0b = blockIdx.x * 128;

    if (tid < 64) {
        float a = gamma[tid] * g_istd[b * 64 + tid];
        As[tid] = a;
        Cs[tid] = beta[tid] - g_mean[b * 64 + tid] * a;
        dqs[tid] = g_dq[tid]; cqs[tid] = g_cq[tid];
        bos[tid] = bo[tid];
        Zs[tid] = g_Z[b * 64 + tid];
    }
    KVs[tid] = g_KV[b * 512 + tid];
#pragma unroll
    for (int i = 0; i < 2; i++)
        ((float4*)wq)[tid + i * 512] = ((const float4*)g_Wqf)[tid + i * 512];
    __syncthreads();
#pragma unroll
    for (int i = 0; i < 4; i++) {
        int idx = tid + i * 512;
        int f = idx >> 5, c = idx & 31;
        float4 v = *(const float4*)(x + ((size_t)(b * 64 + f)) * Ln + l0b + c * 4);
        float a = As[f], c0 = Cs[f];
        v.x = fmaf(v.x, a, c0); v.y = fmaf(v.y, a, c0);
        v.z = fmaf(v.z, a, c0); v.w = fmaf(v.w, a, c0);
        *(float4*)(xns + f * SR + c * 4) = v;
    }
    __syncthreads();
    if (tid < 128) {
        float s1 = 0.f, s2 = 0.f;
#pragma unroll
        for (int f = 0; f < 64; f++) { float t = xns[f * SR + tid]; s1 += t; s2 = fmaf(t, t, s2); }
        float mu = s1 * (1.f / 64.f);
        mus[tid] = mu;
        rss[tid] = rsqrtf(fmaf(-mu, mu, s2 * (1.f / 64.f)) + 1e-5f);
    }
    __syncthreads();

    int pg = (tid & 15) + 16 * (tid >> 8);
    int eg = (tid >> 4) & 15;
    int e0 = eg * 4;

    float2 mu0 = upk(*(const ull*)(mus + 2 * pg));
    float2 mu1 = upk(*(const ull*)(mus + 2 * pg + 64));
    float2 rs0 = upk(*(const ull*)(rss + 2 * pg));
    float2 rs1 = upk(*(const ull*)(rss + 2 * pg + 64));

    // ---- Q GEMM -> phi -> qb ----
    {
        const float* hb = xns + 2 * pg;
        const float* wp = wq + e0;
        ull a[4][2];
#pragma unroll
        for (int i = 0; i < 4; i++) { a[i][0] = a[i][1] = 0ULL; }
#pragma unroll 8
        for (int k = 0; k < 64; k++) {
            ull h0 = *(const ull*)(hb + k * SR);
            ull h1 = *(const ull*)(hb + k * SR + 64);
            float4 w4 = *(const float4*)(wp + k * 64);
            ull wd[4] = {dup(w4.x), dup(w4.y), dup(w4.z), dup(w4.w)};
#pragma unroll
            for (int i = 0; i < 4; i++) {
                fma2(a[i][0], wd[i], h0);
                fma2(a[i][1], wd[i], h1);
            }
        }
#pragma unroll
        for (int i = 0; i < 4; i++) {
            int e = e0 + i; float dq = dqs[e], cq = cqs[e];
            float2 s0 = upk(a[i][0]), s1 = upk(a[i][1]);
            *(ull*)(qb + e * SR + 2 * pg) =
                pk2(phi_fn(fmaf(rs0.x, s0.x - mu0.x * dq, cq)),
                    phi_fn(fmaf(rs0.y, s0.y - mu0.y * dq, cq)));
            *(ull*)(qb + e * SR + 2 * pg + 64) =
                pk2(phi_fn(fmaf(rs1.x, s1.x - mu1.x * dq, cq)),
                    phi_fn(fmaf(rs1.y, s1.y - mu1.y * dq, cq)));
        }
    }
    __syncthreads();   // q complete; Wq reads done

    // ---- reload w <- WoT; attention (2 heads per thread, own cells) ----
#pragma unroll
    for (int i = 0; i < 2; i++)
        ((float4*)wq)[tid + i * 512] = ((const float4*)g_Wof)[tid + i * 512];
    {
        int la = tid & 127;
        int hgrp = tid >> 7;   // 0..3
#pragma unroll
        for (int t = 0; t < 2; t++) {
            int hh = hgrp * 2 + t;
            float q[8];
#pragma unroll
            for (int d = 0; d < 8; d++) q[d] = qb[(hh * 8 + d) * SR + la];
            float nrm = 1e-6f;
#pragma unroll
            for (int d = 0; d < 8; d++) nrm = fmaf(q[d], Zs[hh * 8 + d], nrm);
            float inv = 1.f / nrm;
#pragma unroll
            for (int j = 0; j < 8; j++) {
                float s = 0.f;
#pragma unroll
                for (int d = 0; d < 8; d++) s = fmaf(q[d], KVs[hh * 64 + d * 8 + j], s);
                qb[(hh * 8 + j) * SR + la] = s * inv;
            }
        }
    }
    __syncthreads();

    // ---- Wo GEMM + bias + residual -> y in qb region (66-ull stride) ----
    {
        const float* hb = qb + 2 * pg;
        const float* wp = wq + e0;
        ull a[4][2];
#pragma unroll
        for (int i = 0; i < 4; i++) { a[i][0] = a[i][1] = 0ULL; }
#pragma unroll 8
        for (int k = 0; k < 64; k++) {
            ull h0 = *(const ull*)(hb + k * SR);
            ull h1 = *(const ull*)(hb + k * SR + 64);
            float4 w4 = *(const float4*)(wp + k * 64);
            ull wd[4] = {dup(w4.x), dup(w4.y), dup(w4.z), dup(w4.w)};
#pragma unroll
            for (int i = 0; i < 4; i++) {
                fma2(a[i][0], wd[i], h0);
                fma2(a[i][1], wd[i], h1);
            }
        }
        ull yo[4][2];
#pragma unroll
        for (int i = 0; i < 4; i++) {
            int fo = e0 + i;
            float bb = bos[fo];
            float2 r0 = upk(*(const ull*)(xns + fo * SR + 2 * pg));
            float2 r1 = upk(*(const ull*)(xns + fo * SR + 2 * pg + 64));
            float2 s0 = upk(a[i][0]), s1 = upk(a[i][1]);
            yo[i][0] = pk2(s0.x + bb + r0.x, s0.y + bb + r0.y);
            yo[i][1] = pk2(s1.x + bb + r1.x, s1.y + bb + r1.y);
        }
        __syncthreads();   // all Wo GEMM reads of qb done
#pragma unroll
        for (int i = 0; i < 4; i++) {
            wy[(e0 + i) * 66 + pg]      = yo[i][0];
            wy[(e0 + i) * 66 + pg + 32] = yo[i][1];
        }
    }
    __syncthreads();   // y complete; residual reads of xns done

    // ---- Wlin slab (96 x 128 floats, contiguous) into wq+xns region ----
#pragma unroll
    for (int i = 0; i < 6; i++) {
        int idx = tid + i * 512;               // 3072 float4 = 96 rows x 32
        int p = idx >> 5, c4 = idx & 31;
        ((float4*)wlu)[(p << 5) + c4] = *(const float4*)(Wlin + (size_t)p * Ln + l0b + c4 * 4);
    }
    __syncthreads();

    // ---- temporal GEMM: M[b,p,f] += sum_l Wlin[p,l] * y[f,l] ----
    int fg = tid & 15, pg2 = tid >> 4;          // 16 f-groups x 32 p-groups
    ull acc2[3][4];
#pragma unroll
    for (int i = 0; i < 3; i++)
#pragma unroll
        for (int k = 0; k < 4; k++) acc2[i][k] = 0ULL;
#pragma unroll 4
    for (int j = 0; j < 64; j += 2) {
        ulonglong2 yv[4], wv[3];
#pragma unroll
        for (int k = 0; k < 4; k++) yv[k] = *(const ulonglong2*)(wy + (fg + 16 * k) * 66 + j);
#pragma unroll
        for (int i = 0; i < 3; i++) wv[i] = *(const ulonglong2*)(wlu + (pg2 + 32 * i) * 64 + j);
#pragma unroll
        for (int i = 0; i < 3; i++)
#pragma unroll
            for (int k = 0; k < 4; k++) {
                fma2(acc2[i][k], wv[i].x, yv[k].x);
                fma2(acc2[i][k], wv[i].y, yv[k].y);
            }
    }
#pragma unroll
    for (int i = 0; i < 3; i++)
#pragma unroll
        for (int k = 0; k < 4; k++) {
            float2 t = upk(acc2[i][k]);
            atomicAdd(&g_M[(b * 96 + pg2 + 32 * i) * 64 + fg + 16 * k], t.x + t.y);
        }
}

// ---------------- kernel 5: denorm + projector ----------------
__global__ void k_epi(const float* __restrict__ gamma, const float* __restrict__ beta,
                      const float* __restrict__ blin, const float* __restrict__ Wp,
                      const float* __restrict__ bp, float* __restrict__ out) {
    int b = blockIdx.x, p = threadIdx.x;
    float bl = blin[p];
    float s = bp[0];
#pragma unroll
    for (int f = 0; f < 64; f++) {
        float y = g_M[(b * 96 + p) * 64 + f] + bl;
        y = (y - beta[f]) / gamma[f];
        y = fmaf(y, g_stdp[b * 64 + f], g_mean[b * 64 + f]);
        s = fmaf(y, Wp[f], s);
    }
    out[b * 96 + p] = s;
}

// ---------------- launch ----------------
extern "C" void kernel_launch(void* const* d_in, const int* in_sizes, int n_in,
                              void* d_out, int out_size) {
    (void)in_sizes; (void)n_in; (void)out_size;
    const float* x     = (const float*)d_in[0];
    const float* gamma = (const float*)d_in[1];
    const float* beta  = (const float*)d_in[2];
    const float* lnw   = (const float*)d_in[3];
    const float* lnb   = (const float*)d_in[4];
    const float* Wq    = (const float*)d_in[5];
    const float* bq    = (const float*)d_in[6];
    const float* Wk    = (const float*)d_in[7];
    const float* bk    = (const float*)d_in[8];
    const float* Wv    = (const float*)d_in[9];
    const float* bv    = (const float*)d_in[10];
    const float* Wo    = (const float*)d_in[11];
    const float* bo    = (const float*)d_in[12];
    const float* Wlin  = (const float*)d_in[13];
    const float* blin  = (const float*)d_in[14];
    const float* Wp    = (const float*)d_in[15];
    const float* bp    = (const float*)d_in[16];
    float* out = (float*)d_out;

    const int SMB_KV = (2 * 64 * SR + 8192) * 4;   // 100352 B
    const int SMB_QO = (4096 + 2 * 64 * SR) * 4;   // 83968 B
    cudaFuncSetAttribute(k_kv, cudaFuncAttributeMaxDynamicSharedMemorySize, SMB_KV);
    cudaFuncSetAttribute(k_qo, cudaFuncAttributeMaxDynamicSharedMemorySize, SMB_QO);

    k_zero<<<768, 256>>>();
    k_prep<<<1, 256>>>(lnw, lnb, Wq, bq, Wk, bk, Wv, bv, Wo);
    k_stats<<<Bn * Fn, 256>>>(x);
    k_kv<<<dim3(Ln / 128, Bn), 512, SMB_KV>>>(x, gamma, beta);
    k_qo<<<dim3(Ln / 128, Bn), 512, SMB_QO>>>(x, gamma, beta, bo, Wlin);
    k_epi<<<Bn, Pn>>>(gamma, beta, blin, Wp, bp, out);
}